// round 1
// baseline (speedup 1.0000x reference)
#include <cuda_runtime.h>

// SeathruNeRF RGB renderer, fused single-pass.
// One warp per ray (R=16384), S=256 samples, lane l handles samples c*32+l.
// 7 scan fields: dd, dd+dc_c*delta (x3), dd+bs_c*delta (x3).
// exp(-exclusive_cumsum) gives T, T*direct_att, T*backscattering directly.

#define FULL 0xffffffffu
#define S_SAMPLES 256

__device__ __forceinline__ float clip01(float x) {
    return fminf(fmaxf(x, 0.0f), 1.0f);
}

__global__ __launch_bounds__(256)
void seathru_kernel(const float* __restrict__ orgb,
                    const float* __restrict__ mrgb,
                    const float* __restrict__ dc,
                    const float* __restrict__ bsc,
                    const float* __restrict__ dens,
                    const float* __restrict__ delt,
                    float* __restrict__ out,
                    int R)
{
    const int gwarp = (blockIdx.x * blockDim.x + threadIdx.x) >> 5;
    if (gwarp >= R) return;
    const int lane = threadIdx.x & 31;
    const int r = gwarp;

    // per-ray input bases
    const int base1 = r * S_SAMPLES;        // scalar fields
    const int base3 = r * S_SAMPLES * 3;    // rgb fields

    // output layout (floats):
    // [0,3R)      rgb
    // [3R,6R)     restored
    // [6R,9R)     direct
    // [9R,12R)    backscatter
    // [12R, 12R+RS)        object_transmittance
    // [12R+RS, 12R+2RS)    object_alphas
    // [12R+2RS, 12R+3RS)   object_weights
    // [12R+3RS, 15R+3RS)   direct_coeffs[:,0,:]
    // [15R+3RS, 18R+3RS)   backscatter_coeffs[:,0,:]
    // [18R+3RS, 19R+3RS)   object_mask
    const long long RS = (long long)R * S_SAMPLES;
    float* outT = out + 12LL * R + (long long)r * S_SAMPLES;
    float* outA = outT + RS;
    float* outW = outA + RS;

    float carry0 = 0.f, carry1 = 0.f, carry2 = 0.f, carry3 = 0.f;
    float carry4 = 0.f, carry5 = 0.f, carry6 = 0.f;

    // accumulators: restored(3), direct(3), backscatter(3), mask(1)
    float a_rx = 0.f, a_ry = 0.f, a_rz = 0.f;
    float a_dx = 0.f, a_dy = 0.f, a_dz = 0.f;
    float a_bx = 0.f, a_by = 0.f, a_bz = 0.f;
    float a_m  = 0.f;

    float dc0x = 0.f, dc0y = 0.f, dc0z = 0.f;
    float bs0x = 0.f, bs0y = 0.f, bs0z = 0.f;

    #pragma unroll
    for (int c = 0; c < S_SAMPLES / 32; c++) {
        const int s = c * 32 + lane;

        const float d   = delt[base1 + s];
        const float rho = dens[base1 + s];

        const float dcx = dc[base3 + 3 * s + 0];
        const float dcy = dc[base3 + 3 * s + 1];
        const float dcz = dc[base3 + 3 * s + 2];
        const float bx  = bsc[base3 + 3 * s + 0];
        const float by  = bsc[base3 + 3 * s + 1];
        const float bz  = bsc[base3 + 3 * s + 2];
        const float ox  = orgb[base3 + 3 * s + 0];
        const float oy  = orgb[base3 + 3 * s + 1];
        const float oz  = orgb[base3 + 3 * s + 2];
        const float mx  = mrgb[base3 + 3 * s + 0];
        const float my  = mrgb[base3 + 3 * s + 1];
        const float mz  = mrgb[base3 + 3 * s + 2];

        if (c == 0 && lane == 0) {
            dc0x = dcx; dc0y = dcy; dc0z = dcz;
            bs0x = bx;  bs0y = by;  bs0z = bz;
        }

        const float dd = d * rho;
        const float bdx = bx * d, bdy = by * d, bdz = bz * d;

        // 7 scan fields
        float f0 = dd;
        float f1 = dd + dcx * d;
        float f2 = dd + dcy * d;
        float f3 = dd + dcz * d;
        float f4 = dd + bdx;
        float f5 = dd + bdy;
        float f6 = dd + bdz;

        // inclusive Kogge-Stone warp scan, 7 fields interleaved for ILP
        float i0 = f0, i1 = f1, i2 = f2, i3 = f3, i4 = f4, i5 = f5, i6 = f6;
        #pragma unroll
        for (int off = 1; off < 32; off <<= 1) {
            float n0 = __shfl_up_sync(FULL, i0, off);
            float n1 = __shfl_up_sync(FULL, i1, off);
            float n2 = __shfl_up_sync(FULL, i2, off);
            float n3 = __shfl_up_sync(FULL, i3, off);
            float n4 = __shfl_up_sync(FULL, i4, off);
            float n5 = __shfl_up_sync(FULL, i5, off);
            float n6 = __shfl_up_sync(FULL, i6, off);
            if (lane >= off) {
                i0 += n0; i1 += n1; i2 += n2; i3 += n3;
                i4 += n4; i5 += n5; i6 += n6;
            }
        }

        // exclusive prefix with running carry
        const float e0 = carry0 + i0 - f0;
        const float e1 = carry1 + i1 - f1;
        const float e2 = carry2 + i2 - f2;
        const float e3 = carry3 + i3 - f3;
        const float e4 = carry4 + i4 - f4;
        const float e5 = carry5 + i5 - f5;
        const float e6 = carry6 + i6 - f6;

        carry0 += __shfl_sync(FULL, i0, 31);
        carry1 += __shfl_sync(FULL, i1, 31);
        carry2 += __shfl_sync(FULL, i2, 31);
        carry3 += __shfl_sync(FULL, i3, 31);
        carry4 += __shfl_sync(FULL, i4, 31);
        carry5 += __shfl_sync(FULL, i5, 31);
        carry6 += __shfl_sync(FULL, i6, 31);

        // pointwise
        const float T     = __expf(-e0);
        const float alpha = 1.0f - __expf(-dd);
        const float w     = T * alpha;

        outT[s] = T;
        outA[s] = alpha;
        outW[s] = w;

        a_m  += w;
        a_rx += w * ox;
        a_ry += w * oy;
        a_rz += w * oz;

        // direct weights: exp(-exclcum(dd + dc_c*d)) * alpha
        a_dx += __expf(-e1) * alpha * ox;
        a_dy += __expf(-e2) * alpha * oy;
        a_dz += __expf(-e3) * alpha * oz;

        // backscatter weights: exp(-exclcum(dd + bs_c*d)) * (1 - exp(-bs_c*d))
        a_bx += __expf(-e4) * (1.0f - __expf(-bdx)) * mx;
        a_by += __expf(-e5) * (1.0f - __expf(-bdy)) * my;
        a_bz += __expf(-e6) * (1.0f - __expf(-bdz)) * mz;
    }

    // warp butterfly reduce of the 10 accumulators
    #pragma unroll
    for (int off = 16; off >= 1; off >>= 1) {
        a_rx += __shfl_xor_sync(FULL, a_rx, off);
        a_ry += __shfl_xor_sync(FULL, a_ry, off);
        a_rz += __shfl_xor_sync(FULL, a_rz, off);
        a_dx += __shfl_xor_sync(FULL, a_dx, off);
        a_dy += __shfl_xor_sync(FULL, a_dy, off);
        a_dz += __shfl_xor_sync(FULL, a_dz, off);
        a_bx += __shfl_xor_sync(FULL, a_bx, off);
        a_by += __shfl_xor_sync(FULL, a_by, off);
        a_bz += __shfl_xor_sync(FULL, a_bz, off);
        a_m  += __shfl_xor_sync(FULL, a_m,  off);
    }

    if (lane == 0) {
        float* o_rgb  = out + 0LL;
        float* o_rest = out + 3LL * R;
        float* o_dir  = out + 6LL * R;
        float* o_bs   = out + 9LL * R;
        float* o_dc0  = out + 12LL * R + 3LL * RS;
        float* o_bs0  = out + 15LL * R + 3LL * RS;
        float* o_mask = out + 18LL * R + 3LL * RS;

        o_rgb[3 * r + 0] = clip01(a_dx + a_bx);
        o_rgb[3 * r + 1] = clip01(a_dy + a_by);
        o_rgb[3 * r + 2] = clip01(a_dz + a_bz);

        o_rest[3 * r + 0] = clip01(a_rx);
        o_rest[3 * r + 1] = clip01(a_ry);
        o_rest[3 * r + 2] = clip01(a_rz);

        o_dir[3 * r + 0] = clip01(a_dx);
        o_dir[3 * r + 1] = clip01(a_dy);
        o_dir[3 * r + 2] = clip01(a_dz);

        o_bs[3 * r + 0] = clip01(a_bx);
        o_bs[3 * r + 1] = clip01(a_by);
        o_bs[3 * r + 2] = clip01(a_bz);

        o_dc0[3 * r + 0] = dc0x;
        o_dc0[3 * r + 1] = dc0y;
        o_dc0[3 * r + 2] = dc0z;

        o_bs0[3 * r + 0] = bs0x;
        o_bs0[3 * r + 1] = bs0y;
        o_bs0[3 * r + 2] = bs0z;

        o_mask[r] = clip01(a_m);
    }
}

extern "C" void kernel_launch(void* const* d_in, const int* in_sizes, int n_in,
                              void* d_out, int out_size) {
    const float* orgb = (const float*)d_in[0];
    const float* mrgb = (const float*)d_in[1];
    const float* dc   = (const float*)d_in[2];
    const float* bsc  = (const float*)d_in[3];
    const float* dens = (const float*)d_in[4];
    const float* delt = (const float*)d_in[5];
    float* out = (float*)d_out;

    const int R = in_sizes[4] / S_SAMPLES;   // densities is R*S elements

    const int threads = 256;               // 8 warps = 8 rays per block
    const int blocks = (R * 32 + threads - 1) / threads;
    seathru_kernel<<<blocks, threads>>>(orgb, mrgb, dc, bsc, dens, delt, out, R);
}